// round 2
// baseline (speedup 1.0000x reference)
#include <cuda_runtime.h>
#include <math.h>

#define B_   64
#define T_   256
#define D_   512
#define U_   512
#define G3   1536   // 3*U

// ---------------- device scratch (static: no runtime allocation) ----------
__device__ float g_GX[2][T_][B_][G3];     // e@W + b_in, per direction, original t index
__device__ float g_GHp[4][2][B_][G3];     // k-chunk partial sums of h@Uw
__device__ float g_H[2][B_][U_];          // hidden state
__device__ unsigned int g_bar_count = 0;
__device__ unsigned int g_bar_gen   = 0;

// ---------------- software grid barrier (all blocks resident) -------------
__device__ __forceinline__ void grid_sync(unsigned nb) {
    volatile unsigned* vgen = (volatile unsigned*)&g_bar_gen;
    __syncthreads();
    if (threadIdx.x == 0) {
        unsigned gen = *vgen;
        __threadfence();                       // order gen-read & prior stores before arrive
        if (atomicAdd(&g_bar_count, 1u) == nb - 1u) {
            g_bar_count = 0u;
            __threadfence();
            atomicAdd(&g_bar_gen, 1u);
        } else {
            while (*vgen == gen) { __nanosleep(64); }
        }
        __threadfence();                       // acquire
    }
    __syncthreads();
}

// ======================================================================
// Kernel 1: GX[dir][t][b][:] = emb[x[b][t]] @ W_dir + b_in
// Tiled SGEMM, block tile 64(rows=batch, t fixed per block) x 64 cols, BK=16
// ======================================================================
__global__ __launch_bounds__(256)
void k_input_gemm(const int* __restrict__ x,
                  const float* __restrict__ emb,
                  const float* __restrict__ Wf,
                  const float* __restrict__ bf,
                  const float* __restrict__ Wb,
                  const float* __restrict__ bb)
{
    const int jt  = blockIdx.x;     // 0..23  (column tile)
    const int t   = blockIdx.y;     // 0..255 (time step == row tile, since B_==64)
    const int dir = blockIdx.z;     // 0..1
    const float* __restrict__ W    = dir ? Wb : Wf;
    const float* __restrict__ bin  = dir ? bb : bf;   // row 0 = input bias

    __shared__ float As_t[16][68];   // [k][row] transposed A tile (padded)
    __shared__ float Bs[16][64];     // [k][col]
    __shared__ int   tok[64];

    const int tid = threadIdx.x;
    if (tid < 64) tok[tid] = x[tid * T_ + t];
    __syncthreads();

    const int tx = tid & 15;         // col group (4 cols)
    const int ty = tid >> 4;         // row group (4 rows)
    const int j0 = jt * 64;

    float acc[4][4];
#pragma unroll
    for (int r = 0; r < 4; ++r)
#pragma unroll
        for (int c = 0; c < 4; ++c) acc[r][c] = 0.f;

    for (int k0 = 0; k0 < D_; k0 += 16) {
        // load A tile (embedding gather), store transposed
        {
            int li = tid * 4;            // 0..1023
            int i  = li >> 4;            // row 0..63
            int kb = li & 15;            // 0,4,8,12
            float4 v = *(const float4*)&emb[(size_t)tok[i] * D_ + k0 + kb];
            As_t[kb + 0][i] = v.x;
            As_t[kb + 1][i] = v.y;
            As_t[kb + 2][i] = v.z;
            As_t[kb + 3][i] = v.w;
        }
        // load B tile
        {
            int li = tid * 4;
            int k  = li >> 6;            // 0..15
            int j  = li & 63;
            float4 v = *(const float4*)&W[(size_t)(k0 + k) * G3 + j0 + j];
            *(float4*)&Bs[k][j] = v;
        }
        __syncthreads();
#pragma unroll
        for (int k = 0; k < 16; ++k) {
            float4 av = *(const float4*)&As_t[k][ty * 4];
            float4 bv = *(const float4*)&Bs[k][tx * 4];
            acc[0][0] += av.x * bv.x; acc[0][1] += av.x * bv.y; acc[0][2] += av.x * bv.z; acc[0][3] += av.x * bv.w;
            acc[1][0] += av.y * bv.x; acc[1][1] += av.y * bv.y; acc[1][2] += av.y * bv.z; acc[1][3] += av.y * bv.w;
            acc[2][0] += av.z * bv.x; acc[2][1] += av.z * bv.y; acc[2][2] += av.z * bv.z; acc[2][3] += av.z * bv.w;
            acc[3][0] += av.w * bv.x; acc[3][1] += av.w * bv.y; acc[3][2] += av.w * bv.z; acc[3][3] += av.w * bv.w;
        }
        __syncthreads();
    }

    // epilogue: add input bias, store
#pragma unroll
    for (int r = 0; r < 4; ++r) {
        int b = ty * 4 + r;
        int j = j0 + tx * 4;
        float4 o;
        o.x = acc[r][0] + bin[j + 0];
        o.y = acc[r][1] + bin[j + 1];
        o.z = acc[r][2] + bin[j + 2];
        o.w = acc[r][3] + bin[j + 3];
        *(float4*)&g_GX[dir][t][b][j] = o;
    }
}

// ======================================================================
// Kernel 2: persistent bidirectional GRU recurrence.
// 128 blocks = dir(2) x batch-tile(2 of 32) x unit-tile(8 of 64) x k-chunk(4 of 128)
// Per step: phase A (partial h@Uw) -> barrier -> phase B (gates, h update, out) -> barrier
// ======================================================================
__global__ __launch_bounds__(256, 1)
void k_recurrence(const int* __restrict__ x,
                  const float* __restrict__ Uf,
                  const float* __restrict__ Ub,
                  const float* __restrict__ bf,
                  const float* __restrict__ bb,
                  float* __restrict__ out)
{
    const int bid = blockIdx.x;     // 0..127
    const int tid = threadIdx.x;    // 0..255
    const int kc  = bid & 3;
    const int ut  = (bid >> 2) & 7;
    const int bt  = (bid >> 5) & 1;
    const int dir = bid >> 6;
    const int b0 = bt * 32, u0 = ut * 64, k0 = kc * 128;
    const float* __restrict__ Uw = dir ? Ub : Uf;

    __shared__ float h_s[32][128];      // [b_local][k_local]
    __shared__ float u_s[32 * 192];     // [kk][gate][64 units]

    // init H = 0 (must be deterministic per launch)
    if (ut == 0) {
        for (int j = tid; j < 32 * 128; j += 256) {
            int b = j >> 7, k = j & 127;
            g_H[dir][b0 + b][k0 + k] = 0.f;
        }
    }
    grid_sync(128);

    const int tu = tid & 31;     // unit pair: u0 + 2*tu, +1
    const int tb = tid >> 5;     // batch quad: b0 + 4*tb ..

    float* __restrict__ state = out + (size_t)B_ * T_ * 1024;

    for (int s = 0; s < T_; ++s) {
        // ---------------- phase A: partial gh = h @ Uw (this k-chunk) ----
        // load h slice [32 x 128] (vectorized, L2-coherent)
        for (int j4 = tid; j4 < 1024; j4 += 256) {
            int b  = j4 >> 5;
            int kv = (j4 & 31) * 4;
            float4 v = __ldcg((const float4*)&g_H[dir][b0 + b][k0 + kv]);
            *(float4*)&h_s[b][kv] = v;
        }

        float acc[3][4][2];
#pragma unroll
        for (int g = 0; g < 3; ++g)
#pragma unroll
            for (int i = 0; i < 4; ++i) { acc[g][i][0] = 0.f; acc[g][i][1] = 0.f; }

        for (int ks = 0; ks < 4; ++ks) {
            __syncthreads();
            // stage Uw sub-tile: 32 k x 3 gates x 64 units
            for (int v = tid; v < 1536; v += 256) {
                int kk  = v / 48;
                int rem = v - kk * 48;
                int g   = rem >> 4;
                int q   = (rem & 15) * 4;
                float4 w = *(const float4*)&Uw[(size_t)(k0 + ks * 32 + kk) * G3 + g * 512 + u0 + q];
                *(float4*)&u_s[kk * 192 + g * 64 + q] = w;
            }
            __syncthreads();
#pragma unroll 4
            for (int kk = 0; kk < 32; ++kk) {
                float h0v = h_s[tb * 4 + 0][ks * 32 + kk];
                float h1v = h_s[tb * 4 + 1][ks * 32 + kk];
                float h2v = h_s[tb * 4 + 2][ks * 32 + kk];
                float h3v = h_s[tb * 4 + 3][ks * 32 + kk];
#pragma unroll
                for (int g = 0; g < 3; ++g) {
                    float2 w = *(const float2*)&u_s[kk * 192 + g * 64 + 2 * tu];
                    acc[g][0][0] += h0v * w.x; acc[g][0][1] += h0v * w.y;
                    acc[g][1][0] += h1v * w.x; acc[g][1][1] += h1v * w.y;
                    acc[g][2][0] += h2v * w.x; acc[g][2][1] += h2v * w.y;
                    acc[g][3][0] += h3v * w.x; acc[g][3][1] += h3v * w.y;
                }
            }
        }
        // store partials
#pragma unroll
        for (int g = 0; g < 3; ++g)
#pragma unroll
            for (int i = 0; i < 4; ++i) {
                int b = b0 + tb * 4 + i;
                float2 w = make_float2(acc[g][i][0], acc[g][i][1]);
                __stcg((float2*)&g_GHp[kc][dir][b][g * 512 + u0 + 2 * tu], w);
            }
        grid_sync(128);

        // ---------------- phase B: gates + state update + output ---------
#pragma unroll
        for (int r = 0; r < 2; ++r) {
            int idx = bid * 256 + tid + r * 32768;   // 0..65535
            int u   = idx & 511;
            int b   = (idx >> 9) & 63;
            int d2  = idx >> 15;
            int t   = d2 ? (T_ - 1 - s) : s;
            bool m  = (x[b * T_ + t] != 0);

            const float* __restrict__ brr = (d2 ? bb : bf) + G3;  // recurrent bias
            float gz = brr[u], gr = brr[512 + u], gh = brr[1024 + u];
#pragma unroll
            for (int kcc = 0; kcc < 4; ++kcc) {
                gz += __ldcg(&g_GHp[kcc][d2][b][u]);
                gr += __ldcg(&g_GHp[kcc][d2][b][512 + u]);
                gh += __ldcg(&g_GHp[kcc][d2][b][1024 + u]);
            }
            const float* __restrict__ gx = &g_GX[d2][t][b][0];
            float xz = gx[u], xr = gx[512 + u], xh = gx[1024 + u];
            float hold = __ldcg(&g_H[d2][b][u]);

            float z  = 1.f / (1.f + expf(-(xz + gz)));
            float rr = 1.f / (1.f + expf(-(xr + gr)));
            float hc = tanhf(xh + rr * gh);
            float hn = z * hold + (1.f - z) * hc;
            hn = m ? hn : hold;

            __stcg(&g_H[d2][b][u], hn);
            out[((size_t)b * T_ + t) * 1024 + d2 * 512 + u] = hn;   // out_t == h_t
            if (s == T_ - 1)
                state[(size_t)b * 1024 + d2 * 512 + u] = hn;
        }
        grid_sync(128);
    }
}

// ======================================================================
// Kernel 3: LayerNorm over last dim (1024) of out, in place
// ======================================================================
__global__ __launch_bounds__(256)
void k_layernorm(float* __restrict__ out,
                 const float* __restrict__ gamma,
                 const float* __restrict__ beta)
{
    const int row = blockIdx.x;                 // 0..16383
    float* p = out + (size_t)row * 1024;
    const int tid = threadIdx.x;

    float4 v = *(const float4*)&p[tid * 4];
    float s = v.x + v.y + v.z + v.w;
    float q = v.x * v.x + v.y * v.y + v.z * v.z + v.w * v.w;
#pragma unroll
    for (int o = 16; o; o >>= 1) {
        s += __shfl_xor_sync(0xFFFFFFFFu, s, o);
        q += __shfl_xor_sync(0xFFFFFFFFu, q, o);
    }
    __shared__ float ss[8], qq[8];
    __shared__ float mean_s, rstd_s;
    if ((tid & 31) == 0) { ss[tid >> 5] = s; qq[tid >> 5] = q; }
    __syncthreads();
    if (tid == 0) {
        float S = 0.f, Q = 0.f;
#pragma unroll
        for (int i = 0; i < 8; ++i) { S += ss[i]; Q += qq[i]; }
        float mean = S * (1.f / 1024.f);
        float var  = Q * (1.f / 1024.f) - mean * mean;
        mean_s = mean;
        rstd_s = rsqrtf(var + 1e-3f);
    }
    __syncthreads();
    float mean = mean_s, rstd = rstd_s;
    float4 g  = *(const float4*)&gamma[tid * 4];
    float4 be = *(const float4*)&beta[tid * 4];
    v.x = (v.x - mean) * rstd * g.x + be.x;
    v.y = (v.y - mean) * rstd * g.y + be.y;
    v.z = (v.z - mean) * rstd * g.z + be.z;
    v.w = (v.w - mean) * rstd * g.w + be.w;
    *(float4*)&p[tid * 4] = v;
}

// ======================================================================
extern "C" void kernel_launch(void* const* d_in, const int* in_sizes, int n_in,
                              void* d_out, int out_size)
{
    const int*   x     = (const int*)  d_in[0];
    const float* emb   = (const float*)d_in[1];
    const float* Wf    = (const float*)d_in[2];
    const float* Uf    = (const float*)d_in[3];
    const float* bf    = (const float*)d_in[4];
    const float* Wb    = (const float*)d_in[5];
    const float* Ub    = (const float*)d_in[6];
    const float* bb    = (const float*)d_in[7];
    const float* gamma = (const float*)d_in[8];
    const float* beta  = (const float*)d_in[9];
    float* out = (float*)d_out;

    dim3 g1(G3 / 64, T_, 2);
    k_input_gemm<<<g1, 256>>>(x, emb, Wf, bf, Wb, bb);
    k_recurrence<<<128, 256>>>(x, Uf, Ub, bf, bb, out);
    k_layernorm<<<B_ * T_, 256>>>(out, gamma, beta);
}

// round 4
// speedup vs baseline: 1.3312x; 1.3312x over previous
#include <cuda_runtime.h>
#include <math.h>

#define B_   64
#define T_   256
#define D_   512
#define U_   512
#define G3   1536   // 3*U
#define GHC  4      // partial k-chunks for recurrence

// ---------------- device scratch (static: no runtime allocation) ----------
__device__ float g_GX[2][T_][B_][G3];      // e@W + b_in, per direction
__device__ float g_GHp[GHC][2][B_][G3];    // k-chunk partial sums of h@Uw
__device__ float g_H[2][B_][U_];           // hidden state
__device__ unsigned int g_bar_count = 0;
__device__ unsigned int g_bar_gen   = 0;

// ---------------- software grid barrier (all blocks resident) -------------
__device__ __forceinline__ void grid_sync(unsigned nb) {
    volatile unsigned* vgen = (volatile unsigned*)&g_bar_gen;
    __syncthreads();
    if (threadIdx.x == 0) {
        unsigned gen = *vgen;
        __threadfence();                       // order gen-read & prior stores before arrive
        if (atomicAdd(&g_bar_count, 1u) == nb - 1u) {
            g_bar_count = 0u;
            __threadfence();
            atomicAdd(&g_bar_gen, 1u);
        } else {
            while (*vgen == gen) { __nanosleep(64); }
        }
        __threadfence();                       // acquire
    }
    __syncthreads();
}

// ======================================================================
// Kernel 1: GX[dir][t][b][:] = emb[x[b][t]] @ W_dir + b_in
// (identical to the round-2 passing version)
// ======================================================================
__global__ __launch_bounds__(256)
void k_input_gemm(const int* __restrict__ x,
                  const float* __restrict__ emb,
                  const float* __restrict__ Wf,
                  const float* __restrict__ bf,
                  const float* __restrict__ Wb,
                  const float* __restrict__ bb)
{
    const int jt  = blockIdx.x;     // 0..23  (column tile)
    const int t   = blockIdx.y;     // 0..255 (time step == row tile, since B_==64)
    const int dir = blockIdx.z;     // 0..1
    const float* __restrict__ W    = dir ? Wb : Wf;
    const float* __restrict__ bin  = dir ? bb : bf;   // row 0 = input bias

    __shared__ float As_t[16][68];   // [k][row] transposed A tile (padded)
    __shared__ float Bs[16][64];     // [k][col]
    __shared__ int   tok[64];

    const int tid = threadIdx.x;
    if (tid < 64) tok[tid] = x[tid * T_ + t];
    __syncthreads();

    const int tx = tid & 15;         // col group (4 cols)
    const int ty = tid >> 4;         // row group (4 rows)
    const int j0 = jt * 64;

    float acc[4][4];
#pragma unroll
    for (int r = 0; r < 4; ++r)
#pragma unroll
        for (int c = 0; c < 4; ++c) acc[r][c] = 0.f;

    for (int k0 = 0; k0 < D_; k0 += 16) {
        // load A tile (embedding gather), store transposed
        {
            int li = tid * 4;            // 0..1023
            int i  = li >> 4;            // row 0..63
            int kb = li & 15;            // 0,4,8,12
            float4 v = *(const float4*)&emb[(size_t)tok[i] * D_ + k0 + kb];
            As_t[kb + 0][i] = v.x;
            As_t[kb + 1][i] = v.y;
            As_t[kb + 2][i] = v.z;
            As_t[kb + 3][i] = v.w;
        }
        // load B tile
        {
            int li = tid * 4;
            int k  = li >> 6;            // 0..15
            int j  = li & 63;
            float4 v = *(const float4*)&W[(size_t)(k0 + k) * G3 + j0 + j];
            *(float4*)&Bs[k][j] = v;
        }
        __syncthreads();
#pragma unroll
        for (int k = 0; k < 16; ++k) {
            float4 av = *(const float4*)&As_t[k][ty * 4];
            float4 bv = *(const float4*)&Bs[k][tx * 4];
            acc[0][0] += av.x * bv.x; acc[0][1] += av.x * bv.y; acc[0][2] += av.x * bv.z; acc[0][3] += av.x * bv.w;
            acc[1][0] += av.y * bv.x; acc[1][1] += av.y * bv.y; acc[1][2] += av.y * bv.z; acc[1][3] += av.y * bv.w;
            acc[2][0] += av.z * bv.x; acc[2][1] += av.z * bv.y; acc[2][2] += av.z * bv.z; acc[2][3] += av.z * bv.w;
            acc[3][0] += av.w * bv.x; acc[3][1] += av.w * bv.y; acc[3][2] += av.w * bv.z; acc[3][3] += av.w * bv.w;
        }
        __syncthreads();
    }

    // epilogue: add input bias, store
#pragma unroll
    for (int r = 0; r < 4; ++r) {
        int b = ty * 4 + r;
        int j = j0 + tx * 4;
        float4 o;
        o.x = acc[r][0] + bin[j + 0];
        o.y = acc[r][1] + bin[j + 1];
        o.z = acc[r][2] + bin[j + 2];
        o.w = acc[r][3] + bin[j + 3];
        *(float4*)&g_GX[dir][t][b][j] = o;
    }
}

// ======================================================================
// Kernel 2: persistent bidirectional GRU recurrence.
// 128 blocks = dir(2) x batch-tile(2 of 32) x unit-tile(8 of 64) x k-chunk(4 of 128)
// CHANGE vs round 2: the Uw slice (128k x 192 outputs = 96KB) is loaded into
// shared memory ONCE before the time loop instead of re-staged every step.
// Inner loop / thread mapping / phase B are byte-identical to round 2.
// ======================================================================
__global__ __launch_bounds__(256, 1)
void k_recurrence(const int* __restrict__ x,
                  const float* __restrict__ Uf,
                  const float* __restrict__ Ub,
                  const float* __restrict__ bf,
                  const float* __restrict__ bb,
                  float* __restrict__ out)
{
    extern __shared__ float smem_f[];
    float* h_s = smem_f;                 // [32][128]
    float* u_s = smem_f + 32 * 128;      // [128][192]  (k-major, gate*64+unit)

    const int bid = blockIdx.x;     // 0..127
    const int tid = threadIdx.x;    // 0..255
    const int kc  = bid & 3;
    const int ut  = (bid >> 2) & 7;
    const int bt  = (bid >> 5) & 1;
    const int dir = bid >> 6;
    const int b0 = bt * 32, u0 = ut * 64, k0 = kc * 128;
    const float* __restrict__ Uw = dir ? Ub : Uf;

    // persistent Uw slice: u_s[k*192 + g*64 + q] = Uw[(k0+k)*G3 + g*512 + u0 + q]
    for (int v = tid; v < 128 * 48; v += 256) {          // float4 granules
        int k   = v / 48;
        int rem = v - k * 48;
        int g   = rem >> 4;
        int q   = (rem & 15) * 4;
        *(float4*)&u_s[k * 192 + g * 64 + q] =
            *(const float4*)&Uw[(size_t)(k0 + k) * G3 + g * 512 + u0 + q];
    }

    // init H = 0 (must be deterministic per launch)
    if (ut == 0) {
        for (int j = tid; j < 32 * 128; j += 256) {
            int b = j >> 7, k = j & 127;
            g_H[dir][b0 + b][k0 + k] = 0.f;
        }
    }
    grid_sync(128);

    const int tu = tid & 31;     // unit pair: u0 + 2*tu, +1
    const int tb = tid >> 5;     // batch quad: b0 + 4*tb ..

    float* __restrict__ state = out + (size_t)B_ * T_ * 1024;

    for (int s = 0; s < T_; ++s) {
        // ---- stage h (global -> smem) ------------------------------------
        for (int j4 = tid; j4 < 1024; j4 += 256) {
            int b  = j4 >> 5;
            int kv = (j4 & 31) * 4;
            float4 v = __ldcg((const float4*)&g_H[dir][b0 + b][k0 + kv]);
            *(float4*)&h_s[b * 128 + kv] = v;
        }
        __syncthreads();

        // ---- phase A: partial gh = h @ Uw (persistent smem weights) ------
        float acc[3][4][2];
#pragma unroll
        for (int g = 0; g < 3; ++g)
#pragma unroll
            for (int i = 0; i < 4; ++i) { acc[g][i][0] = 0.f; acc[g][i][1] = 0.f; }

#pragma unroll 4
        for (int kk = 0; kk < 128; ++kk) {
            float h0v = h_s[(tb * 4 + 0) * 128 + kk];
            float h1v = h_s[(tb * 4 + 1) * 128 + kk];
            float h2v = h_s[(tb * 4 + 2) * 128 + kk];
            float h3v = h_s[(tb * 4 + 3) * 128 + kk];
#pragma unroll
            for (int g = 0; g < 3; ++g) {
                float2 w = *(const float2*)&u_s[kk * 192 + g * 64 + 2 * tu];
                acc[g][0][0] += h0v * w.x; acc[g][0][1] += h0v * w.y;
                acc[g][1][0] += h1v * w.x; acc[g][1][1] += h1v * w.y;
                acc[g][2][0] += h2v * w.x; acc[g][2][1] += h2v * w.y;
                acc[g][3][0] += h3v * w.x; acc[g][3][1] += h3v * w.y;
            }
        }
        __syncthreads();   // h_s reads done before next step's staging

        // store partials
#pragma unroll
        for (int g = 0; g < 3; ++g)
#pragma unroll
            for (int i = 0; i < 4; ++i) {
                int b = b0 + tb * 4 + i;
                float2 w = make_float2(acc[g][i][0], acc[g][i][1]);
                __stcg((float2*)&g_GHp[kc][dir][b][g * 512 + u0 + 2 * tu], w);
            }
        grid_sync(128);

        // ---- phase B: gates + state update + output ----------------------
#pragma unroll
        for (int r = 0; r < 2; ++r) {
            int idx = bid * 256 + tid + r * 32768;   // 0..65535
            int u   = idx & 511;
            int b   = (idx >> 9) & 63;
            int d2  = idx >> 15;
            int t   = d2 ? (T_ - 1 - s) : s;
            bool m  = (x[b * T_ + t] != 0);

            const float* __restrict__ brr = (d2 ? bb : bf) + G3;  // recurrent bias
            float gz = brr[u], gr = brr[512 + u], gh = brr[1024 + u];
#pragma unroll
            for (int c = 0; c < GHC; ++c) {
                gz += __ldcg(&g_GHp[c][d2][b][u]);
                gr += __ldcg(&g_GHp[c][d2][b][512 + u]);
                gh += __ldcg(&g_GHp[c][d2][b][1024 + u]);
            }
            const float* __restrict__ gx = &g_GX[d2][t][b][0];
            float xz = gx[u], xr = gx[512 + u], xh = gx[1024 + u];
            float hold = __ldcg(&g_H[d2][b][u]);

            float z  = 1.f / (1.f + expf(-(xz + gz)));
            float rr = 1.f / (1.f + expf(-(xr + gr)));
            float hc = tanhf(xh + rr * gh);
            float hn = z * hold + (1.f - z) * hc;
            hn = m ? hn : hold;

            __stcg(&g_H[d2][b][u], hn);
            out[((size_t)b * T_ + t) * 1024 + d2 * 512 + u] = hn;   // out_t == h_t
            if (s == T_ - 1)
                state[(size_t)b * 1024 + d2 * 512 + u] = hn;
        }
        grid_sync(128);
    }
}

// ======================================================================
// Kernel 3: LayerNorm over last dim (1024) of out, in place
// ======================================================================
__global__ __launch_bounds__(256)
void k_layernorm(float* __restrict__ out,
                 const float* __restrict__ gamma,
                 const float* __restrict__ beta)
{
    const int row = blockIdx.x;                 // 0..16383
    float* p = out + (size_t)row * 1024;
    const int tid = threadIdx.x;

    float4 v = *(const float4*)&p[tid * 4];
    float s = v.x + v.y + v.z + v.w;
    float q = v.x * v.x + v.y * v.y + v.z * v.z + v.w * v.w;
#pragma unroll
    for (int o = 16; o; o >>= 1) {
        s += __shfl_xor_sync(0xFFFFFFFFu, s, o);
        q += __shfl_xor_sync(0xFFFFFFFFu, q, o);
    }
    __shared__ float ss[8], qq[8];
    __shared__ float mean_s, rstd_s;
    if ((tid & 31) == 0) { ss[tid >> 5] = s; qq[tid >> 5] = q; }
    __syncthreads();
    if (tid == 0) {
        float S = 0.f, Q = 0.f;
#pragma unroll
        for (int i = 0; i < 8; ++i) { S += ss[i]; Q += qq[i]; }
        float mean = S * (1.f / 1024.f);
        float var  = Q * (1.f / 1024.f) - mean * mean;
        mean_s = mean;
        rstd_s = rsqrtf(var + 1e-3f);
    }
    __syncthreads();
    float mean = mean_s, rstd = rstd_s;
    float4 g  = *(const float4*)&gamma[tid * 4];
    float4 be = *(const float4*)&beta[tid * 4];
    v.x = (v.x - mean) * rstd * g.x + be.x;
    v.y = (v.y - mean) * rstd * g.y + be.y;
    v.z = (v.z - mean) * rstd * g.z + be.z;
    v.w = (v.w - mean) * rstd * g.w + be.w;
    *(float4*)&p[tid * 4] = v;
}

// ======================================================================
extern "C" void kernel_launch(void* const* d_in, const int* in_sizes, int n_in,
                              void* d_out, int out_size)
{
    const int*   x     = (const int*)  d_in[0];
    const float* emb   = (const float*)d_in[1];
    const float* Wf    = (const float*)d_in[2];
    const float* Uf    = (const float*)d_in[3];
    const float* bf    = (const float*)d_in[4];
    const float* Wb    = (const float*)d_in[5];
    const float* Ub    = (const float*)d_in[6];
    const float* bb    = (const float*)d_in[7];
    const float* gamma = (const float*)d_in[8];
    const float* beta  = (const float*)d_in[9];
    float* out = (float*)d_out;

    const int smem2 = 32 * 128 * 4 + 128 * 192 * 4;   // 16KB h_s + 96KB Uw = 112KB
    cudaFuncSetAttribute(k_recurrence, cudaFuncAttributeMaxDynamicSharedMemorySize, smem2);

    dim3 g1(G3 / 64, T_, 2);
    k_input_gemm<<<g1, 256>>>(x, emb, Wf, bf, Wb, bb);
    k_recurrence<<<128, 256, smem2>>>(x, Uf, Ub, bf, bb, out);
    k_layernorm<<<B_ * T_, 256>>>(out, gamma, beta);
}

// round 5
// speedup vs baseline: 1.3725x; 1.0311x over previous
#include <cuda_runtime.h>
#include <math.h>

#define B_   64
#define T_   256
#define D_   512
#define U_   512
#define G3   1536   // 3*U
#define GHC  4      // partial k-chunks for recurrence

typedef unsigned long long ull;

// ---------------- device scratch (static: no runtime allocation) ----------
__device__ float g_GX[2][T_][B_][G3];      // e@W + b_in, per direction
__device__ float g_GHp[GHC][2][B_][G3];    // k-chunk partial sums of h@Uw
__device__ float g_H[2][B_][U_];           // hidden state
__device__ unsigned int g_bar_count = 0;
__device__ unsigned int g_bar_gen   = 0;

// ---------------- f32x2 packed helpers ------------------------------------
__device__ __forceinline__ void fma2(ull& d, ull a, ull b) {
    asm("fma.rn.f32x2 %0, %1, %2, %3;" : "=l"(d) : "l"(a), "l"(b), "l"(d));
}
__device__ __forceinline__ ull dup2(float v) {
    ull r; asm("mov.b64 %0, {%1, %1};" : "=l"(r) : "f"(v)); return r;
}
__device__ __forceinline__ float2 unpk(ull v) {
    float2 f; asm("mov.b64 {%0, %1}, %2;" : "=f"(f.x), "=f"(f.y) : "l"(v)); return f;
}

// ---------------- software grid barrier (all blocks resident) -------------
__device__ __forceinline__ void grid_sync(unsigned nb) {
    volatile unsigned* vgen = (volatile unsigned*)&g_bar_gen;
    __syncthreads();
    if (threadIdx.x == 0) {
        unsigned gen = *vgen;
        __threadfence();                       // order gen-read & prior stores before arrive
        if (atomicAdd(&g_bar_count, 1u) == nb - 1u) {
            g_bar_count = 0u;
            __threadfence();
            atomicAdd(&g_bar_gen, 1u);
        } else {
            while (*vgen == gen) { __nanosleep(64); }
        }
        __threadfence();                       // acquire
    }
    __syncthreads();
}

// ======================================================================
// Kernel 1: GX[dir][t][b][:] = emb[x[b][t]] @ W_dir + b_in
// (identical to the round-2/4 passing version)
// ======================================================================
__global__ __launch_bounds__(256)
void k_input_gemm(const int* __restrict__ x,
                  const float* __restrict__ emb,
                  const float* __restrict__ Wf,
                  const float* __restrict__ bf,
                  const float* __restrict__ Wb,
                  const float* __restrict__ bb)
{
    const int jt  = blockIdx.x;     // 0..23  (column tile)
    const int t   = blockIdx.y;     // 0..255
    const int dir = blockIdx.z;     // 0..1
    const float* __restrict__ W    = dir ? Wb : Wf;
    const float* __restrict__ bin  = dir ? bb : bf;   // row 0 = input bias

    __shared__ float As_t[16][68];   // [k][row] transposed A tile (padded)
    __shared__ float Bs[16][64];     // [k][col]
    __shared__ int   tok[64];

    const int tid = threadIdx.x;
    if (tid < 64) tok[tid] = x[tid * T_ + t];
    __syncthreads();

    const int tx = tid & 15;         // col group (4 cols)
    const int ty = tid >> 4;         // row group (4 rows)
    const int j0 = jt * 64;

    float acc[4][4];
#pragma unroll
    for (int r = 0; r < 4; ++r)
#pragma unroll
        for (int c = 0; c < 4; ++c) acc[r][c] = 0.f;

    for (int k0 = 0; k0 < D_; k0 += 16) {
        {
            int li = tid * 4;            // 0..1023
            int i  = li >> 4;            // row 0..63
            int kb = li & 15;            // 0,4,8,12
            float4 v = *(const float4*)&emb[(size_t)tok[i] * D_ + k0 + kb];
            As_t[kb + 0][i] = v.x;
            As_t[kb + 1][i] = v.y;
            As_t[kb + 2][i] = v.z;
            As_t[kb + 3][i] = v.w;
        }
        {
            int li = tid * 4;
            int k  = li >> 6;            // 0..15
            int j  = li & 63;
            float4 v = *(const float4*)&W[(size_t)(k0 + k) * G3 + j0 + j];
            *(float4*)&Bs[k][j] = v;
        }
        __syncthreads();
#pragma unroll
        for (int k = 0; k < 16; ++k) {
            float4 av = *(const float4*)&As_t[k][ty * 4];
            float4 bv = *(const float4*)&Bs[k][tx * 4];
            acc[0][0] += av.x * bv.x; acc[0][1] += av.x * bv.y; acc[0][2] += av.x * bv.z; acc[0][3] += av.x * bv.w;
            acc[1][0] += av.y * bv.x; acc[1][1] += av.y * bv.y; acc[1][2] += av.y * bv.z; acc[1][3] += av.y * bv.w;
            acc[2][0] += av.z * bv.x; acc[2][1] += av.z * bv.y; acc[2][2] += av.z * bv.z; acc[2][3] += av.z * bv.w;
            acc[3][0] += av.w * bv.x; acc[3][1] += av.w * bv.y; acc[3][2] += av.w * bv.z; acc[3][3] += av.w * bv.w;
        }
        __syncthreads();
    }

#pragma unroll
    for (int r = 0; r < 4; ++r) {
        int b = ty * 4 + r;
        int j = j0 + tx * 4;
        float4 o;
        o.x = acc[r][0] + bin[j + 0];
        o.y = acc[r][1] + bin[j + 1];
        o.z = acc[r][2] + bin[j + 2];
        o.w = acc[r][3] + bin[j + 3];
        *(float4*)&g_GX[dir][t][b][j] = o;
    }
}

// ======================================================================
// Kernel 2: persistent bidirectional GRU recurrence.
// 128 blocks = dir(2) x batch-tile(2 of 32) x unit-tile(8 of 64) x k-chunk(4 of 128)
// Uw slice persistent in smem (as in round 4).
// ONLY CHANGE vs round 4: phase-A inner arithmetic uses packed fma.rn.f32x2
// (same loads, same thread mapping, same store addresses).
// ======================================================================
__global__ __launch_bounds__(256, 1)
void k_recurrence(const int* __restrict__ x,
                  const float* __restrict__ Uf,
                  const float* __restrict__ Ub,
                  const float* __restrict__ bf,
                  const float* __restrict__ bb,
                  float* __restrict__ out)
{
    extern __shared__ float smem_f[];
    float* h_s = smem_f;                 // [32][128]
    float* u_s = smem_f + 32 * 128;      // [128][192]  (k-major, gate*64+unit)

    const int bid = blockIdx.x;     // 0..127
    const int tid = threadIdx.x;    // 0..255
    const int kc  = bid & 3;
    const int ut  = (bid >> 2) & 7;
    const int bt  = (bid >> 5) & 1;
    const int dir = bid >> 6;
    const int b0 = bt * 32, u0 = ut * 64, k0 = kc * 128;
    const float* __restrict__ Uw = dir ? Ub : Uf;

    // persistent Uw slice: u_s[k*192 + g*64 + q] = Uw[(k0+k)*G3 + g*512 + u0 + q]
    for (int v = tid; v < 128 * 48; v += 256) {          // float4 granules
        int k   = v / 48;
        int rem = v - k * 48;
        int g   = rem >> 4;
        int q   = (rem & 15) * 4;
        *(float4*)&u_s[k * 192 + g * 64 + q] =
            *(const float4*)&Uw[(size_t)(k0 + k) * G3 + g * 512 + u0 + q];
    }

    // init H = 0 (must be deterministic per launch)
    if (ut == 0) {
        for (int j = tid; j < 32 * 128; j += 256) {
            int b = j >> 7, k = j & 127;
            g_H[dir][b0 + b][k0 + k] = 0.f;
        }
    }
    grid_sync(128);

    const int tu = tid & 31;     // unit pair: u0 + 2*tu, +1
    const int tb = tid >> 5;     // batch quad: b0 + 4*tb ..

    float* __restrict__ state = out + (size_t)B_ * T_ * 1024;

    for (int s = 0; s < T_; ++s) {
        // ---- stage h (global -> smem) ------------------------------------
        for (int j4 = tid; j4 < 1024; j4 += 256) {
            int b  = j4 >> 5;
            int kv = (j4 & 31) * 4;
            float4 v = __ldcg((const float4*)&g_H[dir][b0 + b][k0 + kv]);
            *(float4*)&h_s[b * 128 + kv] = v;
        }
        __syncthreads();

        // ---- phase A: partial gh = h @ Uw (packed f32x2) ------------------
        ull acc[3][4];
#pragma unroll
        for (int g = 0; g < 3; ++g)
#pragma unroll
            for (int i = 0; i < 4; ++i) acc[g][i] = 0ull;

#pragma unroll 4
        for (int kk = 0; kk < 128; ++kk) {
            ull h0v = dup2(h_s[(tb * 4 + 0) * 128 + kk]);
            ull h1v = dup2(h_s[(tb * 4 + 1) * 128 + kk]);
            ull h2v = dup2(h_s[(tb * 4 + 2) * 128 + kk]);
            ull h3v = dup2(h_s[(tb * 4 + 3) * 128 + kk]);
            const float* ur = &u_s[kk * 192 + 2 * tu];
            ull w0 = *(const ull*)(ur);          // gate z, units 2tu..2tu+1
            ull w1 = *(const ull*)(ur + 64);     // gate r
            ull w2 = *(const ull*)(ur + 128);    // gate h
            fma2(acc[0][0], h0v, w0); fma2(acc[0][1], h1v, w0);
            fma2(acc[0][2], h2v, w0); fma2(acc[0][3], h3v, w0);
            fma2(acc[1][0], h0v, w1); fma2(acc[1][1], h1v, w1);
            fma2(acc[1][2], h2v, w1); fma2(acc[1][3], h3v, w1);
            fma2(acc[2][0], h0v, w2); fma2(acc[2][1], h1v, w2);
            fma2(acc[2][2], h2v, w2); fma2(acc[2][3], h3v, w2);
        }
        __syncthreads();   // h_s reads done before next step's staging

        // store partials (same addresses as round 4)
#pragma unroll
        for (int g = 0; g < 3; ++g)
#pragma unroll
            for (int i = 0; i < 4; ++i) {
                int b = b0 + tb * 4 + i;
                float2 w = unpk(acc[g][i]);
                __stcg((float2*)&g_GHp[kc][dir][b][g * 512 + u0 + 2 * tu], w);
            }
        grid_sync(128);

        // ---- phase B: gates + state update + output ----------------------
#pragma unroll
        for (int r = 0; r < 2; ++r) {
            int idx = bid * 256 + tid + r * 32768;   // 0..65535
            int u   = idx & 511;
            int b   = (idx >> 9) & 63;
            int d2  = idx >> 15;
            int t   = d2 ? (T_ - 1 - s) : s;
            bool m  = (x[b * T_ + t] != 0);

            const float* __restrict__ brr = (d2 ? bb : bf) + G3;  // recurrent bias
            float gz = brr[u], gr = brr[512 + u], gh = brr[1024 + u];
#pragma unroll
            for (int c = 0; c < GHC; ++c) {
                gz += __ldcg(&g_GHp[c][d2][b][u]);
                gr += __ldcg(&g_GHp[c][d2][b][512 + u]);
                gh += __ldcg(&g_GHp[c][d2][b][1024 + u]);
            }
            const float* __restrict__ gx = &g_GX[d2][t][b][0];
            float xz = gx[u], xr = gx[512 + u], xh = gx[1024 + u];
            float hold = __ldcg(&g_H[d2][b][u]);

            float z  = 1.f / (1.f + expf(-(xz + gz)));
            float rr = 1.f / (1.f + expf(-(xr + gr)));
            float hc = tanhf(xh + rr * gh);
            float hn = z * hold + (1.f - z) * hc;
            hn = m ? hn : hold;

            __stcg(&g_H[d2][b][u], hn);
            out[((size_t)b * T_ + t) * 1024 + d2 * 512 + u] = hn;   // out_t == h_t
            if (s == T_ - 1)
                state[(size_t)b * 1024 + d2 * 512 + u] = hn;
        }
        grid_sync(128);
    }
}

// ======================================================================
// Kernel 3: LayerNorm over last dim (1024) of out, in place
// ======================================================================
__global__ __launch_bounds__(256)
void k_layernorm(float* __restrict__ out,
                 const float* __restrict__ gamma,
                 const float* __restrict__ beta)
{
    const int row = blockIdx.x;                 // 0..16383
    float* p = out + (size_t)row * 1024;
    const int tid = threadIdx.x;

    float4 v = *(const float4*)&p[tid * 4];
    float s = v.x + v.y + v.z + v.w;
    float q = v.x * v.x + v.y * v.y + v.z * v.z + v.w * v.w;
#pragma unroll
    for (int o = 16; o; o >>= 1) {
        s += __shfl_xor_sync(0xFFFFFFFFu, s, o);
        q += __shfl_xor_sync(0xFFFFFFFFu, q, o);
    }
    __shared__ float ss[8], qq[8];
    __shared__ float mean_s, rstd_s;
    if ((tid & 31) == 0) { ss[tid >> 5] = s; qq[tid >> 5] = q; }
    __syncthreads();
    if (tid == 0) {
        float S = 0.f, Q = 0.f;
#pragma unroll
        for (int i = 0; i < 8; ++i) { S += ss[i]; Q += qq[i]; }
        float mean = S * (1.f / 1024.f);
        float var  = Q * (1.f / 1024.f) - mean * mean;
        mean_s = mean;
        rstd_s = rsqrtf(var + 1e-3f);
    }
    __syncthreads();
    float mean = mean_s, rstd = rstd_s;
    float4 g  = *(const float4*)&gamma[tid * 4];
    float4 be = *(const float4*)&beta[tid * 4];
    v.x = (v.x - mean) * rstd * g.x + be.x;
    v.y = (v.y - mean) * rstd * g.y + be.y;
    v.z = (v.z - mean) * rstd * g.z + be.z;
    v.w = (v.w - mean) * rstd * g.w + be.w;
    *(float4*)&p[tid * 4] = v;
}

// ======================================================================
extern "C" void kernel_launch(void* const* d_in, const int* in_sizes, int n_in,
                              void* d_out, int out_size)
{
    const int*   x     = (const int*)  d_in[0];
    const float* emb   = (const float*)d_in[1];
    const float* Wf    = (const float*)d_in[2];
    const float* Uf    = (const float*)d_in[3];
    const float* bf    = (const float*)d_in[4];
    const float* Wb    = (const float*)d_in[5];
    const float* Ub    = (const float*)d_in[6];
    const float* bb    = (const float*)d_in[7];
    const float* gamma = (const float*)d_in[8];
    const float* beta  = (const float*)d_in[9];
    float* out = (float*)d_out;

    const int smem2 = 32 * 128 * 4 + 128 * 192 * 4;   // 16KB h_s + 96KB Uw = 112KB
    cudaFuncSetAttribute(k_recurrence, cudaFuncAttributeMaxDynamicSharedMemorySize, smem2);

    dim3 g1(G3 / 64, T_, 2);
    k_input_gemm<<<g1, 256>>>(x, emb, Wf, bf, Wb, bb);
    k_recurrence<<<128, 256, smem2>>>(x, Uf, Ub, bf, bb, out);
    k_layernorm<<<B_ * T_, 256>>>(out, gamma, beta);
}